// round 5
// baseline (speedup 1.0000x reference)
#include <cuda_runtime.h>

// Problem constants
static constexpr int B = 4096;
static constexpr int K = 1024;
static constexpr int C = 10;
static constexpr int M = 19;

// Kernel A tiling: block = 16 batches x 256 k-samples, 256 threads.
// Each thread owns a PAIR of adjacent b (int2 index loads) and 8 k per b.
static constexpr int NBP     = 8;               // b-pairs per block
static constexpr int NB      = 2 * NBP;         // 16 batches per block
static constexpr int NC      = 32;              // k-chunks per block
static constexpr int THREADS = NBP * NC;        // 256
static constexpr int KSPLIT  = 4;               // k-split across blocks
static constexpr int KBLK    = K / KSPLIT;      // 256 k per block
static constexpr int KCHUNK  = KBLK / NC;       // 8 samples per thread per b

static constexpr int TPAD = 101;                // table row stride (coprime w/ 32)

// Cross-block accumulator, zero-initialized at module load.
// Kernel B re-zeroes it after reading -> invariant holds across graph replays.
__device__ float g_scratch[B * M];

__global__ __launch_bounds__(THREADS, 4)
void ised_accum(const float* __restrict__ x1,
                const float* __restrict__ x2,
                const int*   __restrict__ idx1,
                const int*   __restrict__ idx2)
{
    __shared__ float table[NB * TPAD];        // 16 x 10x10 product tables (6.5KB)
    __shared__ float binsE[THREADS * M];      // per-thread bins, even b (19KB)
    __shared__ float binsO[THREADS * M];      // per-thread bins, odd b  (19KB)

    const int tid = threadIdx.x;
    const int b0  = blockIdx.x * NB;
    const int k0  = blockIdx.y * KBLK;

    // ---- Build per-b product tables ----
    for (int e = tid; e < NB * 100; e += THREADS) {
        const int bl = e / 100;
        const int ij = e - bl * 100;
        const int i  = ij / 10;
        const int j  = ij - i * 10;
        table[bl * TPAD + ij] = __ldg(&x1[(b0 + bl) * C + i]) *
                                __ldg(&x2[(b0 + bl) * C + j]);
    }
    for (int e = tid; e < THREADS * M; e += THREADS) {
        binsE[e] = 0.0f;
        binsO[e] = 0.0f;
    }
    __syncthreads();

    // ---- Main loop: 2 samples/iter via int2, two independent bin chains ----
    const int bp = tid & (NBP - 1);           // b-pair id
    const int kc = tid / NBP;                 // k-chunk id
    const int b  = b0 + bp * 2;               // even, 8B-aligned

    const int2* __restrict__ p1 =
        (const int2*)(idx1 + (size_t)(k0 + kc * KCHUNK) * B + b);
    const int2* __restrict__ p2 =
        (const int2*)(idx2 + (size_t)(k0 + kc * KCHUNK) * B + b);

    const float* __restrict__ t0 = table + (bp * 2) * TPAD;
    const float* __restrict__ t1 = t0 + TPAD;
    float* __restrict__ bE = binsE + tid * M;
    float* __restrict__ bO = binsO + tid * M;

    #pragma unroll
    for (int k = 0; k < KCHUNK; k++) {
        const int2 a = __ldg(&p1[(size_t)k * (B / 2)]);
        const int2 c = __ldg(&p2[(size_t)k * (B / 2)]);
        bE[a.x + c.x] += t0[a.x * 10 + c.x];
        bO[a.y + c.y] += t1[a.y * 10 + c.y];
    }
    __syncthreads();

    // ---- Reduce NC partials per (b, m), push to global scratch ----
    for (int e = tid; e < NB * M; e += THREADS) {
        const int bl  = e / M;
        const int m   = e - bl * M;
        const int pr  = bl >> 1;
        const float* __restrict__ src = (bl & 1) ? binsO : binsE;
        float v = 0.0f;
        #pragma unroll
        for (int c2 = 0; c2 < NC; c2++) {
            v += src[(c2 * NBP + pr) * M + m];
        }
        atomicAdd(&g_scratch[(b0 + bl) * M + m], v);
    }
}

// Kernel B: normalize rows from scratch, write out, re-zero scratch.
static constexpr int NB2 = 32;   // rows per block
__global__ __launch_bounds__(256)
void ised_norm(float* __restrict__ out)
{
    __shared__ float s[NB2][M + 1];
    __shared__ float scl[NB2];

    const int tid = threadIdx.x;
    const int r0  = blockIdx.x * NB2;

    for (int e = tid; e < NB2 * M; e += 256) {
        const int bl = e / M;
        const int m  = e - bl * M;
        const int gi = (r0 + bl) * M + m;
        s[bl][m] = g_scratch[gi];
        g_scratch[gi] = 0.0f;   // reset for next replay
    }
    __syncthreads();

    if (tid < NB2) {
        float sq = 0.0f;
        #pragma unroll
        for (int m = 0; m < M; m++) {
            const float v = s[tid][m];
            sq += v * v;
        }
        scl[tid] = 1.0f / fmaxf(sqrtf(sq), 1e-12f);
    }
    __syncthreads();

    for (int e = tid; e < NB2 * M; e += 256) {
        const int bl = e / M;
        const int m  = e - bl * M;
        out[(r0 + bl) * M + m] = s[bl][m] * scl[bl];
    }
}

extern "C" void kernel_launch(void* const* d_in, const int* in_sizes, int n_in,
                              void* d_out, int out_size)
{
    const float* x1   = (const float*)d_in[0];   // [B, C]
    const float* x2   = (const float*)d_in[1];   // [B, C]
    const int*   idx1 = (const int*)d_in[2];     // [K, B]
    const int*   idx2 = (const int*)d_in[3];     // [K, B]
    float*       out  = (float*)d_out;           // [B, M]

    (void)in_sizes; (void)n_in; (void)out_size;

    dim3 gridA(B / NB, KSPLIT);
    ised_accum<<<gridA, THREADS>>>(x1, x2, idx1, idx2);
    ised_norm<<<B / NB2, 256>>>(out);
}